// round 16
// baseline (speedup 1.0000x reference)
#include <cuda_runtime.h>
#include <cstdint>

#define N_PIX 87040

// ---- dynamic smem pool (floats) ----
//  [0     .. 6384)   lum (LR x LPAD; max 76x84)   | inv aliases (<=4160)
//  [6384  .. 13104)  RGB TMA stage (<= 28 x 240)  | hT aliases (<=4864)
//  [13104 .. 13168)  sx
//  [13168 .. 13232)  sy
//  byte 52928:       1 mbarrier
#define OFF_RGB     6384
#define OFF_SX      13104
#define OFF_SY      13168
#define MBAR_BYTE   52928
#define POOL_BYTES  52992

// phase 2 (32-float window, 16 outputs): element m -> output j iff j+2<=m<=j+14
#define C16(vv, m)                                                                 \
    { if ((m) >= 2  && (m) <= 14) o0  += T[(m) >= 8  ? (m)-8  : 8-(m)]  * (vv);    \
      if ((m) >= 3  && (m) <= 15) o1  += T[(m) >= 9  ? (m)-9  : 9-(m)]  * (vv);    \
      if ((m) >= 4  && (m) <= 16) o2  += T[(m) >= 10 ? (m)-10 : 10-(m)] * (vv);    \
      if ((m) >= 5  && (m) <= 17) o3  += T[(m) >= 11 ? (m)-11 : 11-(m)] * (vv);    \
      if ((m) >= 6  && (m) <= 18) o4  += T[(m) >= 12 ? (m)-12 : 12-(m)] * (vv);    \
      if ((m) >= 7  && (m) <= 19) o5  += T[(m) >= 13 ? (m)-13 : 13-(m)] * (vv);    \
      if ((m) >= 8  && (m) <= 20) o6  += T[(m) >= 14 ? (m)-14 : 14-(m)] * (vv);    \
      if ((m) >= 9  && (m) <= 21) o7  += T[(m) >= 15 ? (m)-15 : 15-(m)] * (vv);    \
      if ((m) >= 10 && (m) <= 22) o8  += T[(m) >= 16 ? (m)-16 : 16-(m)] * (vv);    \
      if ((m) >= 11 && (m) <= 23) o9  += T[(m) >= 17 ? (m)-17 : 17-(m)] * (vv);    \
      if ((m) >= 12 && (m) <= 24) o10 += T[(m) >= 18 ? (m)-18 : 18-(m)] * (vv);    \
      if ((m) >= 13 && (m) <= 25) o11 += T[(m) >= 19 ? (m)-19 : 19-(m)] * (vv);    \
      if ((m) >= 14 && (m) <= 26) o12 += T[(m) >= 20 ? (m)-20 : 20-(m)] * (vv);    \
      if ((m) >= 15 && (m) <= 27) o13 += T[(m) >= 21 ? (m)-21 : 21-(m)] * (vv);    \
      if ((m) >= 16 && (m) <= 28) o14 += T[(m) >= 22 ? (m)-22 : 22-(m)] * (vv);    \
      if ((m) >= 17 && (m) <= 29) o15 += T[(m) >= 23 ? (m)-23 : 23-(m)] * (vv); }

// phase 3a (20-float window, 8 outputs): element m -> output j iff j<=m<=j+12
#define C8V(vv, m)                                                                \
    { if ((m) <= 12)              o0 += T[(m) >= 6  ? (m)-6  : 6-(m)]  * (vv);    \
      if ((m) >= 1 && (m) <= 13)  o1 += T[(m) >= 7  ? (m)-7  : 7-(m)]  * (vv);    \
      if ((m) >= 2 && (m) <= 14)  o2 += T[(m) >= 8  ? (m)-8  : 8-(m)]  * (vv);    \
      if ((m) >= 3 && (m) <= 15)  o3 += T[(m) >= 9  ? (m)-9  : 9-(m)]  * (vv);    \
      if ((m) >= 4 && (m) <= 16)  o4 += T[(m) >= 10 ? (m)-10 : 10-(m)] * (vv);    \
      if ((m) >= 5 && (m) <= 17)  o5 += T[(m) >= 11 ? (m)-11 : 11-(m)] * (vv);    \
      if ((m) >= 6 && (m) <= 18)  o6 += T[(m) >= 12 ? (m)-12 : 12-(m)] * (vv);    \
      if ((m) >= 7 && (m) <= 19)  o7 += T[(m) >= 13 ? (m)-13 : 13-(m)] * (vv); }

__device__ __forceinline__ uint32_t smem_u32(const void* p) {
    return (uint32_t)__cvta_generic_to_shared(p);
}
__device__ __forceinline__ void mbar_init(uint32_t mbar, uint32_t cnt) {
    asm volatile("mbarrier.init.shared.b64 [%0], %1;" :: "r"(mbar), "r"(cnt) : "memory");
}
__device__ __forceinline__ void mbar_expect_tx(uint32_t mbar, uint32_t bytes) {
    asm volatile("mbarrier.arrive.expect_tx.shared.b64 _, [%0], %1;" :: "r"(mbar), "r"(bytes) : "memory");
}
__device__ __forceinline__ void mbar_wait0(uint32_t mbar) {
    asm volatile(
        "{\n\t.reg .pred P1;\n\t"
        "WAIT_LOOP_%=:\n\t"
        "mbarrier.try_wait.parity.acquire.cta.shared::cta.b64 P1, [%0], 0, 0x989680;\n\t"
        "@P1 bra.uni WAIT_DONE_%=;\n\t"
        "bra.uni WAIT_LOOP_%=;\n\t"
        "WAIT_DONE_%=:\n\t}"
        :: "r"(mbar) : "memory");
}
__device__ __forceinline__ void tma_bulk(uint32_t dst, const void* src, uint32_t bytes, uint32_t mbar) {
    asm volatile(
        "cp.async.bulk.shared::cluster.global.mbarrier::complete_tx::bytes [%0], [%1], %2, [%3];"
        :: "r"(dst), "l"(src), "r"(bytes), "r"(mbar) : "memory");
}

// W = image width (=height), TS = tile size. Compile-time only.
template<int W, int TS>
__device__ __forceinline__ void run_tile(int tloc, const float* __restrict__ base,
                                         float* __restrict__ obase,
                                         float* __restrict__ pool, int tid)
{
    const float T[7] = { 1.0f, 0.94595947f, 0.80073740f, 0.60653066f,
                         0.41111229f, 0.24935220f, 0.13533528f };
    constexpr int TPR  = W / TS;
    constexpr int LR   = TS + 12;                 // halo rows (76 / 44)
    constexpr int LC   = TS + 16;                 // halo px cols
    constexpr int LPAD = (TS == 64) ? 84 : 52;    // lum row stride (floats)
    constexpr int NQ   = LC / 4;                  // 4-pixel tasks per row (20 / 12)
    constexpr int RPW  = 3 * LC;                  // RGB row words (240 / 144)
    constexpr int RB   = RPW * 4;                 // RGB row bytes (960 / 576)
    constexpr int DIRR = (TS == 64) ? 48 : 28;    // rows via direct LDG
    constexpr int TMAR = LR - DIRR;               // rows via TMA (28 / 16)

    float* lum = pool;
    float* rgb = pool + OFF_RGB;
    float* hT  = pool + OFF_RGB;                  // aliases RGB (dead after P1)
    float* sxs = pool + OFF_SX;
    float* sys = pool + OFF_SY;
    float* inv = pool;                            // aliases lum (dead after P2)

    const int tx0 = (tloc & (TPR - 1)) * TS;
    const int ty0 = (tloc / TPR) * TS;
    const uint32_t mb   = smem_u32((const char*)pool) + MBAR_BYTE;
    const uint32_t rgb0 = smem_u32(rgb);

    constexpr int HI  = 3 * W * W - 4;            // max float4 start (elements)
    constexpr int HIB = 12 * W * W - RB;          // max row-start byte offset

    if (tid == 0) mbar_init(mb, 1);
    if (tid < 2 * TS) {
        int p = tid & (TS - 1);
        int g = (tid < TS ? tx0 : ty0) + p;
        float s = T[0];
        s += (g >= 1 ? T[1] : 0.f) + (g >= 2 ? T[2] : 0.f) + (g >= 3 ? T[3] : 0.f)
           + (g >= 4 ? T[4] : 0.f) + (g >= 5 ? T[5] : 0.f) + (g >= 6 ? T[6] : 0.f);
        int d = W - 1 - g;
        s += (d >= 1 ? T[1] : 0.f) + (d >= 2 ? T[2] : 0.f) + (d >= 3 ? T[3] : 0.f)
           + (d >= 4 ? T[4] : 0.f) + (d >= 5 ? T[5] : 0.f) + (d >= 6 ? T[6] : 0.f);
        if (tid < TS) sxs[p] = s; else sys[p] = s;
    }
    __syncthreads();   // mbar visible before TMA use

    const bool interior = (tx0 >= 8) && (ty0 >= 6) &&
                          (tx0 + TS + 8 <= W) && (ty0 + TS + 6 <= W);

    // ---- issue ALL TMA rows (rows DIRR..LR-1) upfront; single mbarrier ----
    if (tid == 0) {
        mbar_expect_tx(mb, (uint32_t)(TMAR * RB));
#pragma unroll 4
        for (int i = 0; i < TMAR; i++) {
            int gy = ty0 - 6 + DIRR + i;
            int u  = (gy * W + tx0 - 8) * 12;
            u = min(max(u, 0), HIB);
            tma_bulk(rgb0 + (uint32_t)(i * RB), (const char*)base + u, (uint32_t)RB, mb);
        }
    }

    // ---- P1a: direct-LDG luminance for rows 0..DIRR-1 (overlaps TMA) ----
    {
        constexpr int NT = DIRR * NQ;
        if (interior) {
            for (int t = tid; t < NT; t += 512) {
                int r = t / NQ;
                int q = t - r * NQ;
                int u = ((ty0 - 6 + r) * W + tx0 - 8) * 3 + q * 12;
                float4 a = *(const float4*)(base + u);
                float4 b = *(const float4*)(base + u + 4);
                float4 c = *(const float4*)(base + u + 8);
                float4 o;
                o.x = 0.2989f * a.x + 0.587f * a.y + 0.114f * a.z;
                o.y = 0.2989f * a.w + 0.587f * b.x + 0.114f * b.y;
                o.z = 0.2989f * b.z + 0.587f * b.w + 0.114f * c.x;
                o.w = 0.2989f * c.y + 0.587f * c.z + 0.114f * c.w;
                *(float4*)&lum[r * LPAD + 4 * q] = o;
            }
        } else {
            for (int t = tid; t < NT; t += 512) {
                int r = t / NQ;
                int q = t - r * NQ;
                int gy  = ty0 - 6 + r;
                int gx0 = tx0 - 8 + 4 * q;
                int u = (gy * W + gx0) * 3;
                int u0 = min(max(u,     0), HI);
                int u1 = min(max(u + 4, 0), HI);
                int u2 = min(max(u + 8, 0), HI);
                float4 a = *(const float4*)(base + u0);
                float4 b = *(const float4*)(base + u1);
                float4 c = *(const float4*)(base + u2);
                bool ry = (unsigned)gy < (unsigned)W;
                float4 o;
                o.x = (ry && (unsigned)(gx0    ) < (unsigned)W) ? (0.2989f * a.x + 0.587f * a.y + 0.114f * a.z) : 0.f;
                o.y = (ry && (unsigned)(gx0 + 1) < (unsigned)W) ? (0.2989f * a.w + 0.587f * b.x + 0.114f * b.y) : 0.f;
                o.z = (ry && (unsigned)(gx0 + 2) < (unsigned)W) ? (0.2989f * b.z + 0.587f * b.w + 0.114f * c.x) : 0.f;
                o.w = (ry && (unsigned)(gx0 + 3) < (unsigned)W) ? (0.2989f * c.y + 0.587f * c.z + 0.114f * c.w) : 0.f;
                *(float4*)&lum[r * LPAD + 4 * q] = o;
            }
        }
    }

    // ---- P1b: wait TMA, convert staged rows DIRR..LR-1 from smem ----
    mbar_wait0(mb);
    {
        constexpr int NT = TMAR * NQ;
        for (int t = tid; t < NT; t += 512) {
            int i = t / NQ;
            int q = t - i * NQ;
            int rg = DIRR + i;
            const float* row = rgb + i * RPW;
            if (interior) {
                float4 a = *(const float4*)(row + 12 * q);
                float4 b = *(const float4*)(row + 12 * q + 4);
                float4 c = *(const float4*)(row + 12 * q + 8);
                float4 o;
                o.x = 0.2989f * a.x + 0.587f * a.y + 0.114f * a.z;
                o.y = 0.2989f * a.w + 0.587f * b.x + 0.114f * b.y;
                o.z = 0.2989f * b.z + 0.587f * b.w + 0.114f * c.x;
                o.w = 0.2989f * c.y + 0.587f * c.z + 0.114f * c.w;
                *(float4*)&lum[rg * LPAD + 4 * q] = o;
            } else {
                int gy  = ty0 - 6 + rg;
                bool ry = (unsigned)gy < (unsigned)W;
                int u_raw = (gy * W + tx0 - 8) * 12;
                int u_c   = min(max(u_raw, 0), HIB);
                int sh    = ry ? ((u_raw - u_c) >> 2) : 0;   // float shift {-24,0,+24}
                int idx   = 12 * q + sh;
                float4 a = *(const float4*)(row + idx);
                float4 b = *(const float4*)(row + idx + 4);
                float4 c = *(const float4*)(row + idx + 8);
                int gx0 = tx0 - 8 + 4 * q;
                float4 o;
                o.x = (ry && (unsigned)(gx0    ) < (unsigned)W) ? (0.2989f * a.x + 0.587f * a.y + 0.114f * a.z) : 0.f;
                o.y = (ry && (unsigned)(gx0 + 1) < (unsigned)W) ? (0.2989f * a.w + 0.587f * b.x + 0.114f * b.y) : 0.f;
                o.z = (ry && (unsigned)(gx0 + 2) < (unsigned)W) ? (0.2989f * b.z + 0.587f * b.w + 0.114f * c.x) : 0.f;
                o.w = (ry && (unsigned)(gx0 + 3) < (unsigned)W) ? (0.2989f * c.y + 0.587f * c.z + 0.114f * c.w) : 0.f;
                *(float4*)&lum[rg * LPAD + 4 * q] = o;
            }
        }
    }
    __syncthreads();

    // ---- phase 2: horizontal blur; 16 outputs/thread via 8 aligned LDS.128 ----
    {
        constexpr int NG = TS / 16;
        constexpr int NT = NG * LR;
        for (int t = tid; t < NT; t += 512) {
            int g = t / LR;
            int r = t - g * LR;
            const float* row = &lum[r * LPAD + g * 16];
            float o0  = 0.f, o1  = 0.f, o2  = 0.f, o3  = 0.f;
            float o4  = 0.f, o5  = 0.f, o6  = 0.f, o7  = 0.f;
            float o8  = 0.f, o9  = 0.f, o10 = 0.f, o11 = 0.f;
            float o12 = 0.f, o13 = 0.f, o14 = 0.f, o15 = 0.f;
#pragma unroll
            for (int kk = 0; kk < 8; kk++) {
                float4 qv = *(const float4*)(row + 4 * kk);
                C16(qv.x, 4 * kk + 0);
                C16(qv.y, 4 * kk + 1);
                C16(qv.z, 4 * kk + 2);
                C16(qv.w, 4 * kk + 3);
            }
            float* dst = &hT[(g * 16) * LR + r];
            dst[ 0 * LR] = o0;  dst[ 1 * LR] = o1;  dst[ 2 * LR] = o2;  dst[ 3 * LR] = o3;
            dst[ 4 * LR] = o4;  dst[ 5 * LR] = o5;  dst[ 6 * LR] = o6;  dst[ 7 * LR] = o7;
            dst[ 8 * LR] = o8;  dst[ 9 * LR] = o9;  dst[10 * LR] = o10; dst[11 * LR] = o11;
            dst[12 * LR] = o12; dst[13 * LR] = o13; dst[14 * LR] = o14; dst[15 * LR] = o15;
        }
    }
    __syncthreads();

    // ---- phase 3a: vertical blur; 8 rows/thread via 5 aligned LDS.128; dens ----
    {
        constexpr int NT = TS * (TS / 8);
        for (int t = tid; t < NT; t += 512) {
            int c  = t & (TS - 1);
            int r0 = (t / TS) << 3;
            const float* colp = &hT[c * LR + r0];
            float o0 = 0.f, o1 = 0.f, o2 = 0.f, o3 = 0.f;
            float o4 = 0.f, o5 = 0.f, o6 = 0.f, o7 = 0.f;
#pragma unroll
            for (int kk = 0; kk < 5; kk++) {
                float4 qv = *(const float4*)(colp + 4 * kk);
                C8V(qv.x, 4 * kk + 0);
                C8V(qv.y, 4 * kk + 1);
                C8V(qv.z, 4 * kk + 2);
                C8V(qv.w, 4 * kk + 3);
            }
            const float sx = sxs[c];
            float* invp = &inv[r0 * (TS + 1) + c];
#pragma unroll
            for (int j = 0; j < 8; j++) {
                float oj = (j == 0) ? o0 : (j == 1) ? o1 : (j == 2) ? o2 : (j == 3) ? o3
                         : (j == 4) ? o4 : (j == 5) ? o5 : (j == 6) ? o6 : o7;
                float dj = 0.9999f * sys[r0 + j] * sx;
                invp[j * (TS + 1)] = __fdividef(dj, oj + 1e-3f * dj);
            }
        }
    }
    __syncthreads();

    // ---- phase 3b: vectorized divide; TS rows x (TS*3/4) float4 ----
    {
        constexpr int FPR = TS * 3 / 4;
        constexpr int NT  = TS * FPR;
        for (int t = tid; t < NT; t += 512) {
            int row = (TS == 64) ? (((t >> 4) * 21846) >> 16)
                                 : (((t >> 3) * 21846) >> 16);
            int f   = t - row * FPR;
            int u   = f << 2;
            int p0  = (u * 21846) >> 16;
            int fm3 = u - 3 * p0;
            int th  = 3 - fm3;

            const float* invrow = &inv[row * (TS + 1)];
            float iA = invrow[p0];
            float iB = invrow[p0 + 1];

            int goff = ((ty0 + row) * W + tx0) * 3 + u;
            float4 qv = *(const float4*)(base + goff);
            qv.x *= iA;
            qv.y *= (1 < th) ? iA : iB;
            qv.z *= (2 < th) ? iA : iB;
            qv.w *= iB;
            *(float4*)(obase + goff) = qv;
        }
    }
}

__global__ __launch_bounds__(512, 4)
void lln_kernel(const float* __restrict__ x, float* __restrict__ out)
{
    extern __shared__ float pool[];
    const int tile = blockIdx.x;   // 0..21
    const int b    = blockIdx.y;
    const int tid  = threadIdx.x;
    const int bo   = b * (N_PIX * 3);

    if (tile < 16) {
        run_tile<256, 64>(tile,      x + bo,             out + bo,             pool, tid);
    } else if (tile < 20) {
        run_tile<128, 64>(tile - 16, x + bo + 65536 * 3, out + bo + 65536 * 3, pool, tid);
    } else if (tile == 20) {
        run_tile<64, 64> (0,         x + bo + 81920 * 3, out + bo + 81920 * 3, pool, tid);
    } else {
        run_tile<32, 32> (0,         x + bo + 86016 * 3, out + bo + 86016 * 3, pool, tid);
    }
}

extern "C" void kernel_launch(void* const* d_in, const int* in_sizes, int n_in,
                              void* d_out, int out_size)
{
    const float* x = (const float*)d_in[0];
    float* out     = (float*)d_out;
    cudaFuncSetAttribute(lln_kernel, cudaFuncAttributeMaxDynamicSharedMemorySize, POOL_BYTES);
    dim3 grid(22, 128);
    lln_kernel<<<grid, 512, POOL_BYTES>>>(x, out);
}

// round 17
// speedup vs baseline: 1.0913x; 1.0913x over previous
#include <cuda_runtime.h>
#include <cuda_fp16.h>
#include <cstdint>

#define N_PIX 87040

// ---- static smem pool (bytes) ----
//  [0     .. 16640)  lumH (half, LR x 88)   | inv (fp32, TS x TS+1) aliases
//  [16640 .. 27904)  hTH  (half, TS x 88)
//  [27904 .. 28160)  sx (fp32 64)
//  [28160 .. 28416)  sy (fp32 64)
#define OFF_HT   16640
#define OFF_SX   27904
#define OFF_SY   28160
#define POOL_B   28416
#define LPADH    88     // lum row pitch in halfs (44 words: conflict-free class)
#define LRH      88     // hT row pitch in halfs

// phase 2 (32-float window, 16 outputs): element m -> output j iff j+2<=m<=j+14
#define C16(vv, m)                                                                 \
    { if ((m) >= 2  && (m) <= 14) o0  += T[(m) >= 8  ? (m)-8  : 8-(m)]  * (vv);    \
      if ((m) >= 3  && (m) <= 15) o1  += T[(m) >= 9  ? (m)-9  : 9-(m)]  * (vv);    \
      if ((m) >= 4  && (m) <= 16) o2  += T[(m) >= 10 ? (m)-10 : 10-(m)] * (vv);    \
      if ((m) >= 5  && (m) <= 17) o3  += T[(m) >= 11 ? (m)-11 : 11-(m)] * (vv);    \
      if ((m) >= 6  && (m) <= 18) o4  += T[(m) >= 12 ? (m)-12 : 12-(m)] * (vv);    \
      if ((m) >= 7  && (m) <= 19) o5  += T[(m) >= 13 ? (m)-13 : 13-(m)] * (vv);    \
      if ((m) >= 8  && (m) <= 20) o6  += T[(m) >= 14 ? (m)-14 : 14-(m)] * (vv);    \
      if ((m) >= 9  && (m) <= 21) o7  += T[(m) >= 15 ? (m)-15 : 15-(m)] * (vv);    \
      if ((m) >= 10 && (m) <= 22) o8  += T[(m) >= 16 ? (m)-16 : 16-(m)] * (vv);    \
      if ((m) >= 11 && (m) <= 23) o9  += T[(m) >= 17 ? (m)-17 : 17-(m)] * (vv);    \
      if ((m) >= 12 && (m) <= 24) o10 += T[(m) >= 18 ? (m)-18 : 18-(m)] * (vv);    \
      if ((m) >= 13 && (m) <= 25) o11 += T[(m) >= 19 ? (m)-19 : 19-(m)] * (vv);    \
      if ((m) >= 14 && (m) <= 26) o12 += T[(m) >= 20 ? (m)-20 : 20-(m)] * (vv);    \
      if ((m) >= 15 && (m) <= 27) o13 += T[(m) >= 21 ? (m)-21 : 21-(m)] * (vv);    \
      if ((m) >= 16 && (m) <= 28) o14 += T[(m) >= 22 ? (m)-22 : 22-(m)] * (vv);    \
      if ((m) >= 17 && (m) <= 29) o15 += T[(m) >= 23 ? (m)-23 : 23-(m)] * (vv); }

// phase 3a (20-float window, 8 outputs): element m -> output j iff j<=m<=j+12
#define C8V(vv, m)                                                                \
    { if ((m) <= 12)              o0 += T[(m) >= 6  ? (m)-6  : 6-(m)]  * (vv);    \
      if ((m) >= 1 && (m) <= 13)  o1 += T[(m) >= 7  ? (m)-7  : 7-(m)]  * (vv);    \
      if ((m) >= 2 && (m) <= 14)  o2 += T[(m) >= 8  ? (m)-8  : 8-(m)]  * (vv);    \
      if ((m) >= 3 && (m) <= 15)  o3 += T[(m) >= 9  ? (m)-9  : 9-(m)]  * (vv);    \
      if ((m) >= 4 && (m) <= 16)  o4 += T[(m) >= 10 ? (m)-10 : 10-(m)] * (vv);    \
      if ((m) >= 5 && (m) <= 17)  o5 += T[(m) >= 11 ? (m)-11 : 11-(m)] * (vv);    \
      if ((m) >= 6 && (m) <= 18)  o6 += T[(m) >= 12 ? (m)-12 : 12-(m)] * (vv);    \
      if ((m) >= 7 && (m) <= 19)  o7 += T[(m) >= 13 ? (m)-13 : 13-(m)] * (vv); }

// feed C16 with one uint32 (2 halfs at positions m, m+1)
#define C16H2(u, m)                                   \
    { float2 _f = __half22float2(*(__half2*)&(u));    \
      C16(_f.x, (m));  C16(_f.y, (m) + 1); }
#define C8VH2(u, m)                                   \
    { float2 _f = __half22float2(*(__half2*)&(u));    \
      C8V(_f.x, (m));  C8V(_f.y, (m) + 1); }

// W = image width (=height), TS = tile size. Compile-time only.
template<int W, int TS>
__device__ __forceinline__ void run_tile(int tloc, const float* __restrict__ base,
                                         float* __restrict__ obase,
                                         char* __restrict__ pool, int tid)
{
    const float T[7] = { 1.0f, 0.94595947f, 0.80073740f, 0.60653066f,
                         0.41111229f, 0.24935220f, 0.13533528f };
    constexpr int TPR  = W / TS;
    constexpr int LR   = TS + 12;                 // halo rows (76 / 44)
    constexpr int LC   = TS + 16;                 // halo px cols
    constexpr int NQ   = LC / 4;                  // 4-pixel tasks per row (20 / 12)

    __half* lumH = (__half*)pool;                 // [LR][LPADH]
    __half* hTH  = (__half*)(pool + OFF_HT);      // [TS][LRH]
    float*  sxs  = (float*)(pool + OFF_SX);
    float*  sys  = (float*)(pool + OFF_SY);
    float*  inv  = (float*)pool;                  // aliases lumH (dead after P2)

    const int tx0 = (tloc & (TPR - 1)) * TS;
    const int ty0 = (tloc / TPR) * TS;

    constexpr int HI = 3 * W * W - 4;             // max float4 start (elements)

    // ---- dens tables ----
    if (tid < 2 * TS) {
        int p = tid & (TS - 1);
        int g = (tid < TS ? tx0 : ty0) + p;
        float s = T[0];
        s += (g >= 1 ? T[1] : 0.f) + (g >= 2 ? T[2] : 0.f) + (g >= 3 ? T[3] : 0.f)
           + (g >= 4 ? T[4] : 0.f) + (g >= 5 ? T[5] : 0.f) + (g >= 6 ? T[6] : 0.f);
        int d = W - 1 - g;
        s += (d >= 1 ? T[1] : 0.f) + (d >= 2 ? T[2] : 0.f) + (d >= 3 ? T[3] : 0.f)
           + (d >= 4 ? T[4] : 0.f) + (d >= 5 ? T[5] : 0.f) + (d >= 6 ? T[6] : 0.f);
        if (tid < TS) sxs[p] = s; else sys[p] = s;
    }

    // ---- phase 1: luminance gather (R12 pattern), store half4 ----
    {
        constexpr int NT = LR * NQ;
        const bool interior = (tx0 >= 8) && (ty0 >= 6) &&
                              (tx0 + TS + 8 <= W) && (ty0 + TS + 6 <= W);
        int r = tid / NQ;
        int q = tid - r * NQ;
        constexpr int DR = 512 / NQ;
        constexpr int DQ = 512 - DR * NQ;
        if (interior) {
            for (int t = tid; t < NT; t += 512) {
                int u = ((ty0 - 6 + r) * W + tx0 - 8) * 3 + q * 12;
                float4 a = *(const float4*)(base + u);
                float4 b = *(const float4*)(base + u + 4);
                float4 c = *(const float4*)(base + u + 8);
                __half2 h0 = __floats2half2_rn(
                    0.2989f * a.x + 0.587f * a.y + 0.114f * a.z,
                    0.2989f * a.w + 0.587f * b.x + 0.114f * b.y);
                __half2 h1 = __floats2half2_rn(
                    0.2989f * b.z + 0.587f * b.w + 0.114f * c.x,
                    0.2989f * c.y + 0.587f * c.z + 0.114f * c.w);
                uint2 pk = make_uint2(*(uint32_t*)&h0, *(uint32_t*)&h1);
                *(uint2*)&lumH[r * LPADH + 4 * q] = pk;
                q += DQ; r += DR;
                if (q >= NQ) { q -= NQ; r += 1; }
            }
        } else {
            for (int t = tid; t < NT; t += 512) {
                int gy  = ty0 - 6 + r;
                int gx0 = tx0 - 8 + 4 * q;
                int u = (gy * W + gx0) * 3;
                int u0 = min(max(u,     0), HI);
                int u1 = min(max(u + 4, 0), HI);
                int u2 = min(max(u + 8, 0), HI);
                float4 a = *(const float4*)(base + u0);
                float4 b = *(const float4*)(base + u1);
                float4 c = *(const float4*)(base + u2);
                bool ry = (unsigned)gy < (unsigned)W;
                float l0 = (ry && (unsigned)(gx0    ) < (unsigned)W) ? (0.2989f * a.x + 0.587f * a.y + 0.114f * a.z) : 0.f;
                float l1 = (ry && (unsigned)(gx0 + 1) < (unsigned)W) ? (0.2989f * a.w + 0.587f * b.x + 0.114f * b.y) : 0.f;
                float l2 = (ry && (unsigned)(gx0 + 2) < (unsigned)W) ? (0.2989f * b.z + 0.587f * b.w + 0.114f * c.x) : 0.f;
                float l3 = (ry && (unsigned)(gx0 + 3) < (unsigned)W) ? (0.2989f * c.y + 0.587f * c.z + 0.114f * c.w) : 0.f;
                __half2 h0 = __floats2half2_rn(l0, l1);
                __half2 h1 = __floats2half2_rn(l2, l3);
                uint2 pk = make_uint2(*(uint32_t*)&h0, *(uint32_t*)&h1);
                *(uint2*)&lumH[r * LPADH + 4 * q] = pk;
                q += DQ; r += DR;
                if (q >= NQ) { q -= NQ; r += 1; }
            }
        }
    }
    __syncthreads();

    // ---- phase 2: horizontal blur; 16 outputs/thread via 4 aligned LDS.128 ----
    // window = 32 halfs [16g, 16g+32), outputs px cols 16g..16g+15 (need [16g+2,16g+29])
    {
        constexpr int NG = TS / 16;
        constexpr int NT = NG * LR;
        for (int t = tid; t < NT; t += 512) {
            int g = t / LR;
            int r = t - g * LR;
            const __half* row = &lumH[r * LPADH + g * 16];
            float o0  = 0.f, o1  = 0.f, o2  = 0.f, o3  = 0.f;
            float o4  = 0.f, o5  = 0.f, o6  = 0.f, o7  = 0.f;
            float o8  = 0.f, o9  = 0.f, o10 = 0.f, o11 = 0.f;
            float o12 = 0.f, o13 = 0.f, o14 = 0.f, o15 = 0.f;
#pragma unroll
            for (int kk = 0; kk < 4; kk++) {
                uint4 qv = *(const uint4*)(row + 8 * kk);       // 8 halfs
                C16H2(qv.x, 8 * kk + 0);
                C16H2(qv.y, 8 * kk + 2);
                C16H2(qv.z, 8 * kk + 4);
                C16H2(qv.w, 8 * kk + 6);
            }
            __half* dst = &hTH[(g * 16) * LRH + r];
            dst[ 0 * LRH] = __float2half_rn(o0);  dst[ 1 * LRH] = __float2half_rn(o1);
            dst[ 2 * LRH] = __float2half_rn(o2);  dst[ 3 * LRH] = __float2half_rn(o3);
            dst[ 4 * LRH] = __float2half_rn(o4);  dst[ 5 * LRH] = __float2half_rn(o5);
            dst[ 6 * LRH] = __float2half_rn(o6);  dst[ 7 * LRH] = __float2half_rn(o7);
            dst[ 8 * LRH] = __float2half_rn(o8);  dst[ 9 * LRH] = __float2half_rn(o9);
            dst[10 * LRH] = __float2half_rn(o10); dst[11 * LRH] = __float2half_rn(o11);
            dst[12 * LRH] = __float2half_rn(o12); dst[13 * LRH] = __float2half_rn(o13);
            dst[14 * LRH] = __float2half_rn(o14); dst[15 * LRH] = __float2half_rn(o15);
        }
    }
    __syncthreads();

    // ---- phase 3a: vertical blur; 8 rows/thread (20 halfs: 2 LDS.128 + LDS.64) ----
    {
        constexpr int NT = TS * (TS / 8);
        for (int t = tid; t < NT; t += 512) {
            int c  = t & (TS - 1);
            int r0 = (t / TS) << 3;
            const __half* colp = &hTH[c * LRH + r0];   // 16B aligned (r0 mult of 8)
            float o0 = 0.f, o1 = 0.f, o2 = 0.f, o3 = 0.f;
            float o4 = 0.f, o5 = 0.f, o6 = 0.f, o7 = 0.f;
            uint4 qa = *(const uint4*)(colp);          // halfs 0..7
            uint4 qb = *(const uint4*)(colp + 8);      // halfs 8..15
            uint2 qc = *(const uint2*)(colp + 16);     // halfs 16..19
            C8VH2(qa.x, 0);  C8VH2(qa.y, 2);  C8VH2(qa.z, 4);  C8VH2(qa.w, 6);
            C8VH2(qb.x, 8);  C8VH2(qb.y, 10); C8VH2(qb.z, 12); C8VH2(qb.w, 14);
            C8VH2(qc.x, 16); C8VH2(qc.y, 18);
            const float sx = sxs[c];
            float* invp = &inv[r0 * (TS + 1) + c];
#pragma unroll
            for (int j = 0; j < 8; j++) {
                float oj = (j == 0) ? o0 : (j == 1) ? o1 : (j == 2) ? o2 : (j == 3) ? o3
                         : (j == 4) ? o4 : (j == 5) ? o5 : (j == 6) ? o6 : o7;
                float dj = 0.9999f * sys[r0 + j] * sx;
                invp[j * (TS + 1)] = __fdividef(dj, oj + 1e-3f * dj);
            }
        }
    }
    __syncthreads();

    // ---- phase 3b: vectorized divide; TS rows x (TS*3/4) float4 ----
    {
        constexpr int FPR = TS * 3 / 4;
        constexpr int NT  = TS * FPR;
        for (int t = tid; t < NT; t += 512) {
            int row = (TS == 64) ? (((t >> 4) * 21846) >> 16)
                                 : (((t >> 3) * 21846) >> 16);
            int f   = t - row * FPR;
            int u   = f << 2;
            int p0  = (u * 21846) >> 16;
            int fm3 = u - 3 * p0;
            int th  = 3 - fm3;

            const float* invrow = &inv[row * (TS + 1)];
            float iA = invrow[p0];
            float iB = invrow[p0 + 1];

            int goff = ((ty0 + row) * W + tx0) * 3 + u;
            float4 qv = *(const float4*)(base + goff);
            qv.x *= iA;
            qv.y *= (1 < th) ? iA : iB;
            qv.z *= (2 < th) ? iA : iB;
            qv.w *= iB;
            *(float4*)(obase + goff) = qv;
        }
    }
}

__global__ __launch_bounds__(512, 4)
void lln_kernel(const float* __restrict__ x, float* __restrict__ out)
{
    __shared__ __align__(16) char pool[POOL_B];
    const int tile = blockIdx.x;   // 0..21
    const int b    = blockIdx.y;
    const int tid  = threadIdx.x;
    const int bo   = b * (N_PIX * 3);

    if (tile < 16) {
        run_tile<256, 64>(tile,      x + bo,             out + bo,             pool, tid);
    } else if (tile < 20) {
        run_tile<128, 64>(tile - 16, x + bo + 65536 * 3, out + bo + 65536 * 3, pool, tid);
    } else if (tile == 20) {
        run_tile<64, 64> (0,         x + bo + 81920 * 3, out + bo + 81920 * 3, pool, tid);
    } else {
        run_tile<32, 32> (0,         x + bo + 86016 * 3, out + bo + 86016 * 3, pool, tid);
    }
}

extern "C" void kernel_launch(void* const* d_in, const int* in_sizes, int n_in,
                              void* d_out, int out_size)
{
    const float* x = (const float*)d_in[0];
    float* out     = (float*)d_out;
    dim3 grid(22, 128);
    lln_kernel<<<grid, 512>>>(x, out);
}